// round 8
// baseline (speedup 1.0000x reference)
#include <cuda_runtime.h>
#include <cuda_bf16.h>
#include <math.h>

// out = 4 + (1 + exp(-integral)) / sig2
//   sig2     = sigma^2
//   C        = 6*(196 + sig2)*exp(196/sig2)       (4*R^2 = 196, R=7)
//   inv_C    = isinf(C) ? 0 : 1/C
//   integral = inv_C * 0.5 * sig2                 ((1-delta)=0.5)
// derivation:
//   karras = (sig2+0.25)/(0.25*sig2) = 4 + 1/sig2
//   2*new_weight = 2 * exp(-integral)/(4*sig2*0.5) = exp(-integral)/sig2

__device__ __forceinline__ float bns_elem(float s) {
    float s2   = s * s;
    float e    = expf(196.0f / s2);
    float C    = 6.0f * (196.0f + s2) * e;
    float invC = isinf(C) ? 0.0f : (1.0f / C);
    float integral = invC * 0.5f * s2;
    return 4.0f + (1.0f + expf(-integral)) / s2;
}

__global__ void __launch_bounds__(256)
bns_kernel_v4(const float4* __restrict__ in, float4* __restrict__ out, int n4) {
    int i = blockIdx.x * blockDim.x + threadIdx.x;
    if (i < n4) {
        float4 v = in[i];
        float4 r;
        r.x = bns_elem(v.x);
        r.y = bns_elem(v.y);
        r.z = bns_elem(v.z);
        r.w = bns_elem(v.w);
        out[i] = r;
    }
}

__global__ void bns_kernel_tail(const float* __restrict__ in, float* __restrict__ out,
                                int start, int n) {
    int i = start + blockIdx.x * blockDim.x + threadIdx.x;
    if (i < n) out[i] = bns_elem(in[i]);
}

extern "C" void kernel_launch(void* const* d_in, const int* in_sizes, int n_in,
                              void* d_out, int out_size) {
    const float* sigma = (const float*)d_in[0];
    float* out = (float*)d_out;
    int n  = in_sizes[0];
    int n4 = n >> 2;          // vectorized portion
    int rem_start = n4 << 2;

    if (n4 > 0) {
        int threads = 256;
        int blocks = (n4 + threads - 1) / threads;
        bns_kernel_v4<<<blocks, threads>>>((const float4*)sigma, (float4*)out, n4);
    }
    if (rem_start < n) {
        int tail = n - rem_start;
        bns_kernel_tail<<<(tail + 255) / 256, 256>>>(sigma, out, rem_start, n);
    }
}

// round 13
// speedup vs baseline: 1.4852x; 1.4852x over previous
#include <cuda_runtime.h>
#include <cuda_bf16.h>
#include <math.h>

// out = 4 + (1 + exp(-I)) / s2
//   s2 = sigma^2
//   I  = s2 * exp(-196/s2) / (12*(196+s2))        (4R^2=196, (1-delta)=0.5 folded)
// derivation from reference:
//   C = 6*(196+s2)*exp(196/s2);  inv_C = isinf(C) ? 0 : 1/C
//   I = inv_C * 0.5 * s2  ==  s2 * exp(-196/s2) / (12*(196+s2))
//   (computing exp(-196/s2) directly: when C would overflow, the exp underflows
//    to 0 -> I=0 -> same result as the reference's inv_C=0 branch)
//   karras = 4 + 1/s2;  2*new_weight = exp(-I)/s2

__device__ __forceinline__ float bns_elem(float s) {
    float s2  = s * s;
    float rs2 = __fdividef(1.0f, s2);                 // MUFU.RCP + FMUL
    float ex  = __expf(-196.0f * rs2);                // FMUL + MUFU.EX2 (underflows->0 ok)
    float I   = __fdividef(s2 * ex, fmaf(12.0f, s2, 2352.0f));
    float eI  = __expf(-I);
    return fmaf(1.0f + eI, rs2, 4.0f);
}

__global__ void __launch_bounds__(256)
bns_kernel_v4(const float4* __restrict__ in, float4* __restrict__ out, int n4) {
    int i = blockIdx.x * blockDim.x + threadIdx.x;
    if (i < n4) {
        float4 v = in[i];
        float4 r;
        r.x = bns_elem(v.x);
        r.y = bns_elem(v.y);
        r.z = bns_elem(v.z);
        r.w = bns_elem(v.w);
        out[i] = r;
    }
}

__global__ void bns_kernel_tail(const float* __restrict__ in, float* __restrict__ out,
                                int start, int n) {
    int i = start + blockIdx.x * blockDim.x + threadIdx.x;
    if (i < n) out[i] = bns_elem(in[i]);
}

extern "C" void kernel_launch(void* const* d_in, const int* in_sizes, int n_in,
                              void* d_out, int out_size) {
    const float* sigma = (const float*)d_in[0];
    float* out = (float*)d_out;
    int n  = in_sizes[0];
    int n4 = n >> 2;
    int rem_start = n4 << 2;

    if (n4 > 0) {
        int threads = 256;
        int blocks = (n4 + threads - 1) / threads;
        bns_kernel_v4<<<blocks, threads>>>((const float4*)sigma, (float4*)out, n4);
    }
    if (rem_start < n) {
        int tail = n - rem_start;
        bns_kernel_tail<<<(tail + 255) / 256, 256>>>(sigma, out, rem_start, n);
    }
}

// round 16
// speedup vs baseline: 1.6101x; 1.0841x over previous
#include <cuda_runtime.h>
#include <cuda_bf16.h>
#include <math.h>

// out = 4 + (1 + exp(-I))/s2,  I = s2*exp(-196/s2)/(12*(196+s2))
// For sigma in [8,80]: I in [9.6e-4, 0.0784]  ->  exp(-I) ~= 1 - I
// (dropped I^2/2 term contributes < 5e-7 absolute on out ~= 4)
//   => out ~= 4 + 2/s2 - exp(-196/s2)/(12*(196+s2))
// exp(-196/s2) underflow at tiny sigma reproduces reference's inv_C=0 branch.

__device__ __forceinline__ float frcp(float x) {
    float r; asm("rcp.approx.f32 %0, %1;" : "=f"(r) : "f"(x)); return r;
}
__device__ __forceinline__ float fex2(float x) {
    float r; asm("ex2.approx.f32 %0, %1;" : "=f"(r) : "f"(x)); return r;
}

__device__ __forceinline__ float bns_elem(float s) {
    float s2   = s * s;
    float rs2  = frcp(s2);
    float ex   = fex2(-282.76822f * rs2);          // exp(-196/s2), -196*log2(e)
    float rden = frcp(fmaf(12.0f, s2, 2352.0f));   // 1/(12*(196+s2))
    return fmaf(-ex, rden, fmaf(2.0f, rs2, 4.0f));
}

__device__ __forceinline__ float4 bns_vec(float4 v) {
    float4 r;
    r.x = bns_elem(v.x); r.y = bns_elem(v.y);
    r.z = bns_elem(v.z); r.w = bns_elem(v.w);
    return r;
}

// two float4 per thread: independent load->math->store streams for MLP=2
__global__ void __launch_bounds__(256)
bns_kernel_v8(const float4* __restrict__ in, float4* __restrict__ out, int n8, int n4) {
    int i = blockIdx.x * blockDim.x + threadIdx.x;
    if (i < n8) {
        int j = i + n8;
        float4 a = in[i];
        float4 b = in[j];
        out[i] = bns_vec(a);
        out[j] = bns_vec(b);
    }
}

__global__ void bns_kernel_tail(const float* __restrict__ in, float* __restrict__ out,
                                int start, int n) {
    int i = start + blockIdx.x * blockDim.x + threadIdx.x;
    if (i < n) out[i] = bns_elem(in[i]);
}

extern "C" void kernel_launch(void* const* d_in, const int* in_sizes, int n_in,
                              void* d_out, int out_size) {
    const float* sigma = (const float*)d_in[0];
    float* out = (float*)d_out;
    int n  = in_sizes[0];
    int n4 = n >> 2;          // number of float4s
    int n8 = n4 >> 1;         // pairs of float4s
    int done = (n8 << 1) << 2;  // elements covered by the v8 kernel

    if (n8 > 0) {
        int threads = 256;
        int blocks = (n8 + threads - 1) / threads;
        bns_kernel_v8<<<blocks, threads>>>((const float4*)sigma, (float4*)out, n8, n4);
    }
    if (done < n) {
        int tail = n - done;
        bns_kernel_tail<<<(tail + 255) / 256, 256>>>(sigma, out, done, n);
    }
}